// round 15
// baseline (speedup 1.0000x reference)
#include <cuda_runtime.h>
#include <cuda_bf16.h>
#include <math.h>

typedef unsigned long long ull;

// Problem constants
#define B_    8
#define DIN   1024
#define T_    2048
#define K_    8192
#define DCB   8
#define NT    (B_*T_)          // 16384 total time positions
#define NTP   (NT/2)           // 8192 t-pairs
#define DSPLIT 16
#define DCHUNK (DIN/DSPLIT)    // 64
#define KSPLIT 16
#define KP    (K_/KSPLIT)      // 512 codes per partition

// Output layout (flattened tuple, all float32):
// z_q_out [B,1024,T] | commit[B] | cb_loss[B] | indices[B,T] | z_e[B,8,T]
#define OUT_ZQ     0
#define OUT_COMMIT (B_*DIN*T_)
#define OUT_CBL    (OUT_COMMIT + B_)
#define OUT_IDX    (OUT_CBL + B_)
#define OUT_ZE     (OUT_IDX + NT)

// Scratch (device globals; no allocation allowed)
__device__ float g_w_in[DCB*DIN];                    // normalized in weights [c][d]
__device__ __align__(16) float g_w_out[DIN*DCB];     // normalized out weights [o][c]
__device__ __align__(16) float g_cbn[K_*DCB];        // normalized codebook
__device__ __align__(16) float g_sc[K_];             // -0.5*||cn||^2 per code
__device__ __align__(16) float g_encn[NT*DCB];       // normalized encodings
__device__ __align__(16) ull   g_part[DSPLIT*NTP*DCB]; // split-K partials, t-pair packed (8MB)
__device__ float g_cands[KSPLIT*NT];                 // per-tile best score
__device__ int   g_candi[KSPLIT*NT];                 // per-tile best index (exact)
__device__ int   g_idx[NT];                          // final argmin indices
__device__ float g_losssum[B_];                      // per-batch sum of (z_e-z_q)^2

// ---- packed f32x2 helpers ----
__device__ __forceinline__ ull fma2(ull a, ull b, ull c) {
    ull d;
    asm("fma.rn.f32x2 %0, %1, %2, %3;" : "=l"(d) : "l"(a), "l"(b), "l"(c));
    return d;
}
__device__ __forceinline__ ull pk2(float lo, float hi) {
    ull d;
    asm("mov.b64 %0, {%1, %2};" : "=l"(d) : "f"(lo), "f"(hi));
    return d;
}
__device__ __forceinline__ void unpk2(ull p, float& lo, float& hi) {
    asm("mov.b64 {%0, %1}, %2;" : "=f"(lo), "=f"(hi) : "l"(p));
}

// ---------------------------------------------------------------------------
// Kernel W: prep — normalize codebook (+ -sc/2), w_out (plain), w_in.
// ---------------------------------------------------------------------------
__global__ void kprep(const float* __restrict__ in_v,
                      const float* __restrict__ in_g,
                      const float* __restrict__ out_v,
                      const float* __restrict__ out_g,
                      const float* __restrict__ codebook)
{
    int bid = blockIdx.x;
    int tid = threadIdx.x;

    if (bid < 32) {
        int row = bid * 256 + tid;             // 0..8191
        const float4* c4 = (const float4*)codebook + row * 2;
        float4 a = c4[0], b = c4[1];
        float ss = a.x*a.x + a.y*a.y + a.z*a.z + a.w*a.w
                 + b.x*b.x + b.y*b.y + b.z*b.z + b.w*b.w;
        float nm = fmaxf(sqrtf(ss), 1e-12f);
        float inv = 1.0f / nm;
        float4 na = make_float4(a.x*inv, a.y*inv, a.z*inv, a.w*inv);
        float4 nb = make_float4(b.x*inv, b.y*inv, b.z*inv, b.w*inv);
        float4* o4 = (float4*)g_cbn + row * 2;
        o4[0] = na; o4[1] = nb;
        float sc = na.x*na.x + na.y*na.y + na.z*na.z + na.w*na.w
                 + nb.x*nb.x + nb.y*nb.y + nb.z*nb.z + nb.w*nb.w;
        g_sc[row] = -0.5f * sc;
    } else if (bid == 32) {
        for (int o = tid; o < DIN; o += 256) {
            const float4* v4 = (const float4*)out_v + o * 2;
            float4 a = v4[0], b = v4[1];
            float ss = a.x*a.x + a.y*a.y + a.z*a.z + a.w*a.w
                     + b.x*b.x + b.y*b.y + b.z*b.z + b.w*b.w;
            float s = out_g[o] / sqrtf(ss);
            float4* w4 = (float4*)g_w_out + o * 2;
            w4[0] = make_float4(a.x*s, a.y*s, a.z*s, a.w*s);
            w4[1] = make_float4(b.x*s, b.y*s, b.z*s, b.w*s);
        }
    } else {
        __shared__ float norms[DCB];
        int w = tid >> 5, l = tid & 31;
        if (w < DCB) {
            float ss = 0.f;
            const float* vr = in_v + w * DIN;
            for (int j = l; j < DIN; j += 32) { float x = vr[j]; ss = fmaf(x, x, ss); }
            #pragma unroll
            for (int off = 16; off; off >>= 1)
                ss += __shfl_xor_sync(0xffffffffu, ss, off);
            if (l == 0) norms[w] = sqrtf(ss);
        }
        __syncthreads();
        for (int flat = tid; flat < DCB*DIN; flat += 256) {
            int c = flat >> 10;
            g_w_in[flat] = in_g[c] * in_v[flat] / norms[c];
        }
        if (tid < B_) g_losssum[tid] = 0.f;
    }
}

// ---------------------------------------------------------------------------
// Kernel A1: split-K in-projection partials, t-pair vectorized.
// Each thread handles two adjacent t's: z loads are LDG.64, weights are
// dup-packed in smem, accumulators packed (t, t+1). Per-scalar fma order
// identical to the scalar version -> bitwise-identical partials.
// grid (T_/256, B_, DSPLIT), 128 threads.
// ---------------------------------------------------------------------------
__global__ void kinproj(const float* __restrict__ z)
{
    __shared__ __align__(16) ull wd[DCHUNK * DCB];   // dup-packed [j][c], 4KB
    int tid = threadIdx.x;
    int ds  = blockIdx.z;

    #pragma unroll
    for (int e = tid; e < DCHUNK*DCB; e += 128) {
        int c = e & 7;
        int j = e >> 3;
        float w = g_w_in[c*DIN + ds*DCHUNK + j];
        wd[e] = pk2(w, w);
    }
    __syncthreads();

    int tp = blockIdx.x * 128 + tid;          // local t-pair 0..1023
    int b = blockIdx.y;
    const float* zp = z + ((size_t)b * DIN + ds * DCHUNK) * T_ + 2*tp;

    ull acc2[DCB];
    #pragma unroll
    for (int c = 0; c < DCB; c++) acc2[c] = 0ull;

    #pragma unroll 8
    for (int j = 0; j < DCHUNK; j++) {
        ull Z2 = *(const ull*)(zp + (size_t)j * T_);   // (z_t, z_t+1)
        const ulonglong2* wp = (const ulonglong2*)(wd + j*DCB);
        ulonglong2 w01 = wp[0], w23 = wp[1], w45 = wp[2], w67 = wp[3];
        acc2[0] = fma2(w01.x, Z2, acc2[0]);
        acc2[1] = fma2(w01.y, Z2, acc2[1]);
        acc2[2] = fma2(w23.x, Z2, acc2[2]);
        acc2[3] = fma2(w23.y, Z2, acc2[3]);
        acc2[4] = fma2(w45.x, Z2, acc2[4]);
        acc2[5] = fma2(w45.y, Z2, acc2[5]);
        acc2[6] = fma2(w67.x, Z2, acc2[6]);
        acc2[7] = fma2(w67.y, Z2, acc2[7]);
    }

    int tpg = b * (T_/2) + tp;
    ulonglong2* p2 = (ulonglong2*)(g_part + ((size_t)ds * NTP + tpg) * DCB);
    p2[0] = make_ulonglong2(acc2[0], acc2[1]);
    p2[1] = make_ulonglong2(acc2[2], acc2[3]);
    p2[2] = make_ulonglong2(acc2[4], acc2[5]);
    p2[3] = make_ulonglong2(acc2[6], acc2[7]);
}

// ---------------------------------------------------------------------------
// Kernel A2: combine partials (t-pair), add bias, write z_e, normalized enc.
// grid NTP/256 = 32 blocks, 256 threads; one thread per t-pair.
// ---------------------------------------------------------------------------
__global__ void kcombine(const float* __restrict__ in_b,
                         float* __restrict__ out)
{
    int tpg = blockIdx.x * 256 + threadIdx.x;   // 0..8191
    int b = tpg >> 10;
    int t = (tpg & 1023) * 2;

    float2 a[DCB];
    #pragma unroll
    for (int c = 0; c < DCB; c++) a[c] = make_float2(0.f, 0.f);

    #pragma unroll
    for (int ds = 0; ds < DSPLIT; ds++) {
        const float4* p4 = (const float4*)(g_part + ((size_t)ds * NTP + tpg) * DCB);
        #pragma unroll
        for (int h = 0; h < 4; h++) {
            float4 q = p4[h];
            a[2*h].x   += q.x; a[2*h].y   += q.y;   // (c=2h: t, t+1)
            a[2*h+1].x += q.z; a[2*h+1].y += q.w;   // (c=2h+1)
        }
    }

    float ze0[DCB], ze1[DCB];
    float ss0 = 0.f, ss1 = 0.f;
    #pragma unroll
    for (int c = 0; c < DCB; c++) {
        float bb = in_b[c];
        ze0[c] = a[c].x + bb;
        ze1[c] = a[c].y + bb;
        ss0 = fmaf(ze0[c], ze0[c], ss0);
        ss1 = fmaf(ze1[c], ze1[c], ss1);
    }

    #pragma unroll
    for (int c = 0; c < DCB; c++)
        *(float2*)(out + OUT_ZE + ((size_t)b * DCB + c) * T_ + t) = make_float2(ze0[c], ze1[c]);

    float inv0 = 1.0f / fmaxf(sqrtf(ss0), 1e-12f);
    float inv1 = 1.0f / fmaxf(sqrtf(ss1), 1e-12f);
    int tg = b * T_ + t;
    float4* e0 = (float4*)g_encn + (size_t)tg * 2;
    e0[0] = make_float4(ze0[0]*inv0, ze0[1]*inv0, ze0[2]*inv0, ze0[3]*inv0);
    e0[1] = make_float4(ze0[4]*inv0, ze0[5]*inv0, ze0[6]*inv0, ze0[7]*inv0);
    float4* e1 = (float4*)g_encn + (size_t)(tg + 1) * 2;
    e1[0] = make_float4(ze1[0]*inv1, ze1[1]*inv1, ze1[2]*inv1, ze1[3]*inv1);
    e1[1] = make_float4(ze1[4]*inv1, ze1[5]*inv1, ze1[6]*inv1, ze1[7]*inv1);
}

// ---------------------------------------------------------------------------
// Kernel B: per-tile argmax with in-kernel exact index recovery (R10/R8
// measured-best version, unchanged).
// ---------------------------------------------------------------------------
#define NCHUNK 8
#define CHSZ   64
__global__ void __launch_bounds__(128) kargmin(void)
{
    __shared__ __align__(16) float cbs[KP * DCB];   // 16KB
    __shared__ __align__(16) float scs[KP];         // 2KB

    int tid = threadIdx.x;
    int r = tid & 7;
    int g = tid >> 3;                       // group 0..15
    int q0 = blockIdx.x * 128 + g * 8;
    int kp0 = blockIdx.y * KP;

    {
        const float4* g4 = (const float4*)g_cbn + (size_t)kp0 * 2;
        float4* d4 = (float4*)cbs;
        #pragma unroll
        for (int j = tid; j < KP*DCB/4; j += 128) d4[j] = g4[j];
        if (tid < KP/4) ((float4*)scs)[tid] = ((const float4*)(g_sc + kp0))[tid];
    }

    ull E[4][8];
    #pragma unroll
    for (int j = 0; j < 4; j++) {
        const float4* pa = (const float4*)g_encn + (size_t)(q0 + 2*j) * 2;
        const float4* pb = (const float4*)g_encn + (size_t)(q0 + 2*j + 1) * 2;
        float4 a0 = pa[0], a1 = pa[1], b0 = pb[0], b1 = pb[1];
        E[j][0] = pk2(a0.x, b0.x); E[j][1] = pk2(a0.y, b0.y);
        E[j][2] = pk2(a0.z, b0.z); E[j][3] = pk2(a0.w, b0.w);
        E[j][4] = pk2(a1.x, b1.x); E[j][5] = pk2(a1.y, b1.y);
        E[j][6] = pk2(a1.z, b1.z); E[j][7] = pk2(a1.w, b1.w);
    }

    float gbest[8]; int bch[8];
    #pragma unroll
    for (int q = 0; q < 8; q++) { gbest[q] = -3.4e38f; bch[q] = 0; }

    __syncthreads();

    const float4* c4 = (const float4*)cbs;

    for (int c = 0; c < NCHUNK; c++) {
        float cm[8];
        #pragma unroll
        for (int q = 0; q < 8; q++) cm[q] = -3.4e38f;

        #pragma unroll
        for (int i = 0; i < CHSZ/8; i++) {
            int kl = c*CHSZ + i*8 + r;
            float4 ca = c4[kl*2];
            float4 cb = c4[kl*2 + 1];
            float s = scs[kl];
            ull S  = pk2(s, s);
            ull C0 = pk2(ca.x, ca.x), C1 = pk2(ca.y, ca.y);
            ull C2 = pk2(ca.z, ca.z), C3 = pk2(ca.w, ca.w);
            ull C4 = pk2(cb.x, cb.x), C5 = pk2(cb.y, cb.y);
            ull C6 = pk2(cb.z, cb.z), C7 = pk2(cb.w, cb.w);
            #pragma unroll
            for (int j = 0; j < 4; j++) {
                ull p = fma2(E[j][0], C0, fma2(E[j][1], C1, fma2(E[j][2], C2,
                        fma2(E[j][3], C3, fma2(E[j][4], C4, fma2(E[j][5], C5,
                        fma2(E[j][6], C6, fma2(E[j][7], C7, S))))))));
                float lo, hi; unpk2(p, lo, hi);
                cm[2*j]   = fmaxf(cm[2*j],   lo);
                cm[2*j+1] = fmaxf(cm[2*j+1], hi);
            }
        }
        #pragma unroll
        for (int q = 0; q < 8; q++)
            if (cm[q] > gbest[q]) { gbest[q] = cm[q]; bch[q] = c; }
    }

    #pragma unroll
    for (int q = 0; q < 8; q++) {
        float bs = gbest[q];
        #pragma unroll
        for (int off = 4; off; off >>= 1)
            bs = fmaxf(bs, __shfl_xor_sync(0xffffffffu, bs, off));

        int cand = 0x7fffffff;
        if (gbest[q] == bs) {
            const float4* e4 = (const float4*)g_encn + (size_t)(q0 + q) * 2;
            float4 ea = e4[0], eb = e4[1];
            int base = bch[q] * CHSZ + r;
            #pragma unroll
            for (int i = 0; i < CHSZ/8; i++) {
                int kl = base + i*8;
                float4 ca = c4[kl*2];
                float4 cb = c4[kl*2 + 1];
                float v = fmaf(ea.x, ca.x, fmaf(ea.y, ca.y, fmaf(ea.z, ca.z,
                          fmaf(ea.w, ca.w, fmaf(eb.x, cb.x, fmaf(eb.y, cb.y,
                          fmaf(eb.z, cb.z, fmaf(eb.w, cb.w, scs[kl]))))))));
                if (v == bs && kl < cand) cand = kl;
            }
        }
        #pragma unroll
        for (int off = 4; off; off >>= 1)
            cand = min(cand, __shfl_xor_sync(0xffffffffu, cand, off));

        if (r == 0) {
            g_cands[blockIdx.y * NT + q0 + q] = bs;
            g_candi[blockIdx.y * NT + q0 + q] = kp0 + cand;
        }
    }
}

// ---------------------------------------------------------------------------
// Kernel B2: trivial merge of per-tile (score,index), write indices, loss.
// ---------------------------------------------------------------------------
__global__ void kreduce(const float* __restrict__ codebook,
                        float* __restrict__ out)
{
    __shared__ float sloss;
    int tid = threadIdx.x;
    int q = blockIdx.x * 256 + tid;
    int b = q >> 11;
    int t = q & (T_-1);

    if (tid == 0) sloss = 0.f;
    __syncthreads();

    float best = -3.4e38f; int bi = 0x7fffffff;
    #pragma unroll
    for (int p = 0; p < KSPLIT; p++) {
        float v = g_cands[p * NT + q];
        int   i = g_candi[p * NT + q];
        if (v > best || (v == best && i < bi)) { best = v; bi = i; }
    }
    g_idx[q] = bi;
    out[OUT_IDX + q] = (float)bi;

    const float4* q4 = (const float4*)codebook + (size_t)bi * 2;
    float4 qa = q4[0], qb = q4[1];
    float zq[DCB] = {qa.x, qa.y, qa.z, qa.w, qb.x, qb.y, qb.z, qb.w};
    float s = 0.f;
    #pragma unroll
    for (int c = 0; c < DCB; c++) {
        float ze = out[OUT_ZE + ((size_t)b * DCB + c) * T_ + t];
        float d = ze - zq[c];
        s = fmaf(d, d, s);
    }
    #pragma unroll
    for (int off = 16; off; off >>= 1)
        s += __shfl_xor_sync(0xffffffffu, s, off);
    if ((tid & 31) == 0) atomicAdd(&sloss, s);

    __syncthreads();
    if (tid == 0) atomicAdd(&g_losssum[b], sloss);
}

// ---------------------------------------------------------------------------
// Kernel C: out-projection, t-pair vectorized: Z packs = (zst_t, zst_t+1),
// weights dup-packed in smem, STG.64 outputs. Same c-nesting as before.
// grid (T_/512, B_, 16), 256 threads. Block (0,0,0) finalizes losses.
// ---------------------------------------------------------------------------
#define OCH 64
__global__ void koutproj(const float* __restrict__ codebook,
                         const float* __restrict__ out_b,
                         float* __restrict__ out)
{
    __shared__ __align__(16) ull ws2[OCH * DCB];   // dup-packed weights, 4KB
    __shared__ __align__(16) ull obs2[OCH];        // dup-packed bias

    int tid = threadIdx.x;
    int t = (blockIdx.x * 256 + tid) * 2;
    int b = blockIdx.y;
    int obase = blockIdx.z * OCH;

    if (blockIdx.x == 0 && blockIdx.y == 0 && blockIdx.z == 0 && tid < B_) {
        float m = g_losssum[tid] / (float)(DCB * T_);
        out[OUT_COMMIT + tid] = m * 0.005f;
        out[OUT_CBL + tid]    = m * 1.0f;
    }

    #pragma unroll
    for (int e = tid; e < OCH*DCB; e += 256) {
        float w = g_w_out[(size_t)(obase + (e >> 3)) * DCB + (e & 7)];
        ws2[e] = pk2(w, w);
    }
    if (tid < OCH) {
        float bb = out_b[obase + tid];
        obs2[tid] = pk2(bb, bb);
    }

    int ki0 = g_idx[b * T_ + t];
    int ki1 = g_idx[b * T_ + t + 1];
    const float4* p0 = (const float4*)codebook + (size_t)ki0 * 2;
    const float4* p1 = (const float4*)codebook + (size_t)ki1 * 2;
    float4 qa0 = p0[0], qb0 = p0[1], qa1 = p1[0], qb1 = p1[1];
    float zq0[DCB] = {qa0.x, qa0.y, qa0.z, qa0.w, qb0.x, qb0.y, qb0.z, qb0.w};
    float zq1[DCB] = {qa1.x, qa1.y, qa1.z, qa1.w, qb1.x, qb1.y, qb1.z, qb1.w};

    ull Z[DCB];
    #pragma unroll
    for (int c = 0; c < DCB; c++) {
        float2 zep = *(const float2*)(out + OUT_ZE + ((size_t)b * DCB + c) * T_ + t);
        float z0 = zep.x + (zq0[c] - zep.x);   // straight-through forward value
        float z1 = zep.y + (zq1[c] - zep.y);
        Z[c] = pk2(z0, z1);
    }
    __syncthreads();

    float* op = out + OUT_ZQ + ((size_t)b * DIN + obase) * T_ + t;

    #pragma unroll 8
    for (int o = 0; o < OCH; o++) {
        const ulonglong2* wq = (const ulonglong2*)(ws2 + o*DCB);
        ulonglong2 w0 = wq[0], w1 = wq[1], w2 = wq[2], w3 = wq[3];
        ull rp = fma2(w0.x, Z[0], fma2(w0.y, Z[1], fma2(w1.x, Z[2],
                 fma2(w1.y, Z[3], fma2(w2.x, Z[4], fma2(w2.y, Z[5],
                 fma2(w3.x, Z[6], fma2(w3.y, Z[7], obs2[o]))))))));
        float lo, hi; unpk2(rp, lo, hi);
        *(float2*)(op + (size_t)o * T_) = make_float2(lo, hi);
    }
}

// ---------------------------------------------------------------------------
extern "C" void kernel_launch(void* const* d_in, const int* in_sizes, int n_in,
                              void* d_out, int out_size)
{
    const float* z        = (const float*)d_in[0];
    const float* in_v     = (const float*)d_in[1];
    const float* in_g     = (const float*)d_in[2];
    const float* in_b     = (const float*)d_in[3];
    const float* out_v    = (const float*)d_in[4];
    const float* out_g    = (const float*)d_in[5];
    const float* out_b    = (const float*)d_in[6];
    const float* codebook = (const float*)d_in[7];
    float* out = (float*)d_out;

    kprep<<<34, 256>>>(in_v, in_g, out_v, out_g, codebook);
    kinproj<<<dim3(T_/256, B_, DSPLIT), 128>>>(z);
    kcombine<<<NTP/256, 256>>>(in_b, out);
    kargmin<<<dim3(NT/128, KSPLIT), 128>>>();
    kreduce<<<NT/256, 256>>>(codebook, out);
    koutproj<<<dim3(T_/512, B_, DIN/OCH), 256>>>(codebook, out_b, out);
}

// round 16
// speedup vs baseline: 1.0595x; 1.0595x over previous
#include <cuda_runtime.h>
#include <cuda_bf16.h>
#include <math.h>

typedef unsigned long long ull;

// Problem constants
#define B_    8
#define DIN   1024
#define T_    2048
#define K_    8192
#define DCB   8
#define NT    (B_*T_)          // 16384 total time positions
#define DSPLIT 16
#define DCHUNK (DIN/DSPLIT)    // 64
#define KSPLIT 16
#define KP    (K_/KSPLIT)      // 512 codes per partition

// Output layout (flattened tuple, all float32):
// z_q_out [B,1024,T] | commit[B] | cb_loss[B] | indices[B,T] | z_e[B,8,T]
#define OUT_ZQ     0
#define OUT_COMMIT (B_*DIN*T_)
#define OUT_CBL    (OUT_COMMIT + B_)
#define OUT_IDX    (OUT_CBL + B_)
#define OUT_ZE     (OUT_IDX + NT)

// Scratch (device globals; no allocation allowed)
__device__ float g_w_in[DCB*DIN];                    // normalized in weights [c][d]
__device__ __align__(16) float g_w_out[DIN*DCB];     // normalized out weights, o-PAIR packed:
                                                     //   [(o>>1)*16 + c*2 + (o&1)]
__device__ __align__(16) float g_cbn[K_*DCB];        // normalized codebook
__device__ __align__(16) float g_sc[K_];             // -0.5*||cn||^2 per code
__device__ __align__(16) float g_encn[NT*DCB];       // normalized encodings
__device__ __align__(16) float g_part[DSPLIT*NT*DCB];// split-K partials (8MB)
__device__ float g_cands[KSPLIT*NT];                 // per-tile best score
__device__ int   g_candi[KSPLIT*NT];                 // per-tile best index (exact)
__device__ int   g_idx[NT];                          // final argmin indices
__device__ float g_losssum[B_];                      // per-batch sum of (z_e-z_q)^2

// ---- packed f32x2 helpers ----
__device__ __forceinline__ ull fma2(ull a, ull b, ull c) {
    ull d;
    asm("fma.rn.f32x2 %0, %1, %2, %3;" : "=l"(d) : "l"(a), "l"(b), "l"(c));
    return d;
}
__device__ __forceinline__ ull pk2(float lo, float hi) {
    ull d;
    asm("mov.b64 %0, {%1, %2};" : "=l"(d) : "f"(lo), "f"(hi));
    return d;
}
__device__ __forceinline__ void unpk2(ull p, float& lo, float& hi) {
    asm("mov.b64 {%0, %1}, %2;" : "=f"(lo), "=f"(hi) : "l"(p));
}

// ---------------------------------------------------------------------------
// Kernel W: prep — normalize codebook (+ -sc/2), w_out (pair-packed), w_in.
// ---------------------------------------------------------------------------
__global__ void kprep(const float* __restrict__ in_v,
                      const float* __restrict__ in_g,
                      const float* __restrict__ out_v,
                      const float* __restrict__ out_g,
                      const float* __restrict__ codebook)
{
    int bid = blockIdx.x;
    int tid = threadIdx.x;

    if (bid < 32) {
        int row = bid * 256 + tid;             // 0..8191
        const float4* c4 = (const float4*)codebook + row * 2;
        float4 a = c4[0], b = c4[1];
        float ss = a.x*a.x + a.y*a.y + a.z*a.z + a.w*a.w
                 + b.x*b.x + b.y*b.y + b.z*b.z + b.w*b.w;
        float nm = fmaxf(sqrtf(ss), 1e-12f);
        float inv = 1.0f / nm;
        float4 na = make_float4(a.x*inv, a.y*inv, a.z*inv, a.w*inv);
        float4 nb = make_float4(b.x*inv, b.y*inv, b.z*inv, b.w*inv);
        float4* o4 = (float4*)g_cbn + row * 2;
        o4[0] = na; o4[1] = nb;
        float sc = na.x*na.x + na.y*na.y + na.z*na.z + na.w*na.w
                 + nb.x*nb.x + nb.y*nb.y + nb.z*nb.z + nb.w*nb.w;
        g_sc[row] = -0.5f * sc;
    } else if (bid == 32) {
        for (int o = tid; o < DIN; o += 256) {
            const float4* v4 = (const float4*)out_v + o * 2;
            float4 a = v4[0], b = v4[1];
            float ss = a.x*a.x + a.y*a.y + a.z*a.z + a.w*a.w
                     + b.x*b.x + b.y*b.y + b.z*b.z + b.w*b.w;
            float s = out_g[o] / sqrtf(ss);
            float w[DCB] = { a.x*s, a.y*s, a.z*s, a.w*s, b.x*s, b.y*s, b.z*s, b.w*s };
            float* dst = g_w_out + (o >> 1) * 16 + (o & 1);
            #pragma unroll
            for (int c = 0; c < DCB; c++) dst[c*2] = w[c];
        }
    } else {
        __shared__ float norms[DCB];
        int w = tid >> 5, l = tid & 31;
        if (w < DCB) {
            float ss = 0.f;
            const float* vr = in_v + w * DIN;
            for (int j = l; j < DIN; j += 32) { float x = vr[j]; ss = fmaf(x, x, ss); }
            #pragma unroll
            for (int off = 16; off; off >>= 1)
                ss += __shfl_xor_sync(0xffffffffu, ss, off);
            if (l == 0) norms[w] = sqrtf(ss);
        }
        __syncthreads();
        for (int flat = tid; flat < DCB*DIN; flat += 256) {
            int c = flat >> 10;
            g_w_in[flat] = in_g[c] * in_v[flat] / norms[c];
        }
        if (tid < B_) g_losssum[tid] = 0.f;
    }
}

// ---------------------------------------------------------------------------
// Kernel A1: split-K in-projection partials (DSPLIT=16 chunks of 64 dims).
// f32x2-packed accumulators (same per-channel accumulation order -> bitwise
// identical partials to the scalar version). grid.x interleaves (b,ds).
// ---------------------------------------------------------------------------
__global__ void kinproj(const float* __restrict__ z)
{
    __shared__ __align__(16) float wst[DCHUNK * DCB];   // transposed [j][c], 2KB
    int tid = threadIdx.x;
    int ds  = blockIdx.y & (DSPLIT-1);
    int b   = blockIdx.y >> 4;

    for (int e = tid; e < DCHUNK*DCB; e += 128) {
        int c = e >> 6;
        int j = e & (DCHUNK-1);
        wst[j*DCB + c] = g_w_in[c*DIN + ds*DCHUNK + j];
    }
    __syncthreads();

    int t = blockIdx.x * 128 + tid;
    const float* zp = z + ((size_t)b * DIN + ds * DCHUNK) * T_ + t;

    ull acc2[4] = {0ull, 0ull, 0ull, 0ull};   // packed (c,c+1) accumulators

    #pragma unroll 8
    for (int j = 0; j < DCHUNK; j++) {
        float zv = zp[(size_t)j * T_];
        ull Z = pk2(zv, zv);
        const ulonglong2* wp = (const ulonglong2*)(wst + j*DCB);
        ulonglong2 wA = wp[0], wB = wp[1];
        acc2[0] = fma2(wA.x, Z, acc2[0]);
        acc2[1] = fma2(wA.y, Z, acc2[1]);
        acc2[2] = fma2(wB.x, Z, acc2[2]);
        acc2[3] = fma2(wB.y, Z, acc2[3]);
    }

    int tg = b * T_ + t;
    ulonglong2* p2 = (ulonglong2*)(g_part + ((size_t)ds * NT + tg) * DCB);
    p2[0] = make_ulonglong2(acc2[0], acc2[1]);
    p2[1] = make_ulonglong2(acc2[2], acc2[3]);
}

// ---------------------------------------------------------------------------
// Kernel A2: combine partials, add bias, write z_e, write normalized enc.
// 256 blocks x 64 threads (one thread per t) for full-chip wave coverage.
// ---------------------------------------------------------------------------
__global__ void kcombine(const float* __restrict__ in_b,
                         float* __restrict__ out)
{
    int tg = blockIdx.x * 64 + threadIdx.x;
    int b = tg >> 11;
    int t = tg & (T_-1);

    float4 a0 = make_float4(0,0,0,0), a1 = make_float4(0,0,0,0);
    #pragma unroll
    for (int ds = 0; ds < DSPLIT; ds++) {
        const float4* p4 = (const float4*)(g_part + ((size_t)ds * NT + tg) * DCB);
        float4 q0 = p4[0], q1 = p4[1];
        a0.x += q0.x; a0.y += q0.y; a0.z += q0.z; a0.w += q0.w;
        a1.x += q1.x; a1.y += q1.y; a1.z += q1.z; a1.w += q1.w;
    }
    float ze[DCB] = { a0.x + in_b[0], a0.y + in_b[1], a0.z + in_b[2], a0.w + in_b[3],
                      a1.x + in_b[4], a1.y + in_b[5], a1.z + in_b[6], a1.w + in_b[7] };

    float* oz = out + OUT_ZE + (size_t)b * DCB * T_ + t;
    float ss = 0.f;
    #pragma unroll
    for (int c = 0; c < DCB; c++) {
        oz[(size_t)c * T_] = ze[c];
        ss = fmaf(ze[c], ze[c], ss);
    }
    float inv = 1.0f / fmaxf(sqrtf(ss), 1e-12f);
    float4* en4 = (float4*)g_encn + (size_t)tg * 2;
    en4[0] = make_float4(ze[0]*inv, ze[1]*inv, ze[2]*inv, ze[3]*inv);
    en4[1] = make_float4(ze[4]*inv, ze[5]*inv, ze[6]*inv, ze[7]*inv);
}

// ---------------------------------------------------------------------------
// Kernel B: per-tile argmax with in-kernel exact index recovery (R10/R8
// measured-best version, unchanged).
// ---------------------------------------------------------------------------
#define NCHUNK 8
#define CHSZ   64
__global__ void __launch_bounds__(128) kargmin(void)
{
    __shared__ __align__(16) float cbs[KP * DCB];   // 16KB
    __shared__ __align__(16) float scs[KP];         // 2KB

    int tid = threadIdx.x;
    int r = tid & 7;
    int g = tid >> 3;                       // group 0..15
    int q0 = blockIdx.x * 128 + g * 8;
    int kp0 = blockIdx.y * KP;

    {
        const float4* g4 = (const float4*)g_cbn + (size_t)kp0 * 2;
        float4* d4 = (float4*)cbs;
        #pragma unroll
        for (int j = tid; j < KP*DCB/4; j += 128) d4[j] = g4[j];
        if (tid < KP/4) ((float4*)scs)[tid] = ((const float4*)(g_sc + kp0))[tid];
    }

    ull E[4][8];
    #pragma unroll
    for (int j = 0; j < 4; j++) {
        const float4* pa = (const float4*)g_encn + (size_t)(q0 + 2*j) * 2;
        const float4* pb = (const float4*)g_encn + (size_t)(q0 + 2*j + 1) * 2;
        float4 a0 = pa[0], a1 = pa[1], b0 = pb[0], b1 = pb[1];
        E[j][0] = pk2(a0.x, b0.x); E[j][1] = pk2(a0.y, b0.y);
        E[j][2] = pk2(a0.z, b0.z); E[j][3] = pk2(a0.w, b0.w);
        E[j][4] = pk2(a1.x, b1.x); E[j][5] = pk2(a1.y, b1.y);
        E[j][6] = pk2(a1.z, b1.z); E[j][7] = pk2(a1.w, b1.w);
    }

    float gbest[8]; int bch[8];
    #pragma unroll
    for (int q = 0; q < 8; q++) { gbest[q] = -3.4e38f; bch[q] = 0; }

    __syncthreads();

    const float4* c4 = (const float4*)cbs;

    for (int c = 0; c < NCHUNK; c++) {
        float cm[8];
        #pragma unroll
        for (int q = 0; q < 8; q++) cm[q] = -3.4e38f;

        #pragma unroll
        for (int i = 0; i < CHSZ/8; i++) {
            int kl = c*CHSZ + i*8 + r;
            float4 ca = c4[kl*2];
            float4 cb = c4[kl*2 + 1];
            float s = scs[kl];
            ull S  = pk2(s, s);
            ull C0 = pk2(ca.x, ca.x), C1 = pk2(ca.y, ca.y);
            ull C2 = pk2(ca.z, ca.z), C3 = pk2(ca.w, ca.w);
            ull C4 = pk2(cb.x, cb.x), C5 = pk2(cb.y, cb.y);
            ull C6 = pk2(cb.z, cb.z), C7 = pk2(cb.w, cb.w);
            #pragma unroll
            for (int j = 0; j < 4; j++) {
                ull p = fma2(E[j][0], C0, fma2(E[j][1], C1, fma2(E[j][2], C2,
                        fma2(E[j][3], C3, fma2(E[j][4], C4, fma2(E[j][5], C5,
                        fma2(E[j][6], C6, fma2(E[j][7], C7, S))))))));
                float lo, hi; unpk2(p, lo, hi);
                cm[2*j]   = fmaxf(cm[2*j],   lo);
                cm[2*j+1] = fmaxf(cm[2*j+1], hi);
            }
        }
        // strict > keeps the EARLIEST chunk achieving the max (lowest indices)
        #pragma unroll
        for (int q = 0; q < 8; q++)
            if (cm[q] > gbest[q]) { gbest[q] = cm[q]; bch[q] = c; }
    }

    // epilogue: per query, group max + exact index via winning-chunk rescan
    #pragma unroll
    for (int q = 0; q < 8; q++) {
        float bs = gbest[q];
        #pragma unroll
        for (int off = 4; off; off >>= 1)
            bs = fmaxf(bs, __shfl_xor_sync(0xffffffffu, bs, off));

        int cand = 0x7fffffff;
        if (gbest[q] == bs) {
            const float4* e4 = (const float4*)g_encn + (size_t)(q0 + q) * 2;
            float4 ea = e4[0], eb = e4[1];
            int base = bch[q] * CHSZ + r;
            #pragma unroll
            for (int i = 0; i < CHSZ/8; i++) {
                int kl = base + i*8;
                float4 ca = c4[kl*2];
                float4 cb = c4[kl*2 + 1];
                // identical nesting to a packed-chain half
                float v = fmaf(ea.x, ca.x, fmaf(ea.y, ca.y, fmaf(ea.z, ca.z,
                          fmaf(ea.w, ca.w, fmaf(eb.x, cb.x, fmaf(eb.y, cb.y,
                          fmaf(eb.z, cb.z, fmaf(eb.w, cb.w, scs[kl]))))))));
                if (v == bs && kl < cand) cand = kl;
            }
        }
        #pragma unroll
        for (int off = 4; off; off >>= 1)
            cand = min(cand, __shfl_xor_sync(0xffffffffu, cand, off));

        if (r == 0) {
            g_cands[blockIdx.y * NT + q0 + q] = bs;
            g_candi[blockIdx.y * NT + q0 + q] = kp0 + cand;
        }
    }
}

// ---------------------------------------------------------------------------
// Kernel B2: trivial merge of per-tile (score,index), write indices, loss.
// 256 blocks x 64 threads for wave coverage.
// ---------------------------------------------------------------------------
__global__ void kreduce(const float* __restrict__ codebook,
                        float* __restrict__ out)
{
    __shared__ float sloss;
    int tid = threadIdx.x;
    int q = blockIdx.x * 64 + tid;
    int b = q >> 11;
    int t = q & (T_-1);

    if (tid == 0) sloss = 0.f;
    __syncthreads();

    float best = -3.4e38f; int bi = 0x7fffffff;
    #pragma unroll
    for (int p = 0; p < KSPLIT; p++) {
        float v = g_cands[p * NT + q];
        int   i = g_candi[p * NT + q];
        if (v > best || (v == best && i < bi)) { best = v; bi = i; }
    }
    g_idx[q] = bi;
    out[OUT_IDX + q] = (float)bi;

    // loss: sum over 8 dims of (z_e - codebook[bi])^2
    const float4* q4 = (const float4*)codebook + (size_t)bi * 2;
    float4 qa = q4[0], qb = q4[1];
    float zq[DCB] = {qa.x, qa.y, qa.z, qa.w, qb.x, qb.y, qb.z, qb.w};
    float s = 0.f;
    #pragma unroll
    for (int c = 0; c < DCB; c++) {
        float ze = out[OUT_ZE + ((size_t)b * DCB + c) * T_ + t];
        float d = ze - zq[c];
        s = fmaf(d, d, s);
    }
    #pragma unroll
    for (int off = 16; off; off >>= 1)
        s += __shfl_xor_sync(0xffffffffu, s, off);
    if ((tid & 31) == 0) atomicAdd(&sloss, s);

    __syncthreads();
    if (tid == 0) atomicAdd(&g_losssum[b], sloss);
}

// ---------------------------------------------------------------------------
// Kernel C: out-projection, f32x2-packed over o-pairs (o split into 16
// chunks of 64, 256 threads). Block (0,0,0) finalizes the loss outputs.
// ---------------------------------------------------------------------------
#define OCH 64
__global__ void koutproj(const float* __restrict__ codebook,
                         const float* __restrict__ out_b,
                         float* __restrict__ out)
{
    __shared__ __align__(16) float ws[OCH * DCB];   // pair-packed weights, 2KB
    __shared__ __align__(16) float obs[OCH];

    int tid = threadIdx.x;
    int t = blockIdx.x * 256 + tid;
    int b = blockIdx.y;
    int obase = blockIdx.z * OCH;

    if (blockIdx.x == 0 && blockIdx.y == 0 && blockIdx.z == 0 && tid < B_) {
        float m = g_losssum[tid] / (float)(DCB * T_);
        out[OUT_COMMIT + tid] = m * 0.005f;
        out[OUT_CBL + tid]    = m * 1.0f;
    }

    {
        // packed weight region for this o-chunk is contiguous: floats
        // [obase*8, obase*8 + 512)
        const float4* s4 = (const float4*)(g_w_out + obase * DCB);
        float4* d4 = (float4*)ws;
        if (tid < OCH*DCB/4) d4[tid] = s4[tid];
        if (tid >= 128 && tid < 128 + OCH/4)
            ((float4*)obs)[tid - 128] = ((const float4*)(out_b + obase))[tid - 128];
    }

    int ki = g_idx[b * T_ + t];
    const float4* q4 = (const float4*)codebook + (size_t)ki * 2;
    float4 qa = q4[0], qb = q4[1];
    float zq[DCB] = {qa.x, qa.y, qa.z, qa.w, qb.x, qb.y, qb.z, qb.w};
    ull Z[DCB];                       // duplicated straight-through packs
    #pragma unroll
    for (int c = 0; c < DCB; c++) {
        float ze = out[OUT_ZE + ((size_t)b * DCB + c) * T_ + t];
        float zst = ze + (zq[c] - ze);   // straight-through forward value
        Z[c] = pk2(zst, zst);
    }
    __syncthreads();

    const ull* obp = (const ull*)obs;
    float* op = out + OUT_ZQ + ((size_t)b * DIN + obase) * T_ + t;

    #pragma unroll 8
    for (int p = 0; p < OCH/2; p++) {
        const ulonglong2* wq = (const ulonglong2*)ws + p*4;
        ulonglong2 w0 = wq[0], w1 = wq[1], w2 = wq[2], w3 = wq[3];
        ull rp = fma2(w0.x, Z[0], fma2(w0.y, Z[1], fma2(w1.x, Z[2],
                 fma2(w1.y, Z[3], fma2(w2.x, Z[4], fma2(w2.y, Z[5],
                 fma2(w3.x, Z[6], fma2(w3.y, Z[7], obp[p]))))))));
        float lo, hi; unpk2(rp, lo, hi);
        op[(size_t)(2*p)   * T_] = lo;
        op[(size_t)(2*p+1) * T_] = hi;
    }
}

// ---------------------------------------------------------------------------
extern "C" void kernel_launch(void* const* d_in, const int* in_sizes, int n_in,
                              void* d_out, int out_size)
{
    const float* z        = (const float*)d_in[0];
    const float* in_v     = (const float*)d_in[1];
    const float* in_g     = (const float*)d_in[2];
    const float* in_b     = (const float*)d_in[3];
    const float* out_v    = (const float*)d_in[4];
    const float* out_g    = (const float*)d_in[5];
    const float* out_b    = (const float*)d_in[6];
    const float* codebook = (const float*)d_in[7];
    float* out = (float*)d_out;

    kprep<<<34, 256>>>(in_v, in_g, out_v, out_g, codebook);
    kinproj<<<dim3(T_/128, B_*DSPLIT), 128>>>(z);
    kcombine<<<NT/64, 64>>>(in_b, out);
    kargmin<<<dim3(NT/128, KSPLIT), 128>>>();
    kreduce<<<NT/64, 64>>>(codebook, out);
    koutproj<<<dim3(T_/256, B_, DIN/OCH), 256>>>(codebook, out_b, out);
}